// round 17
// baseline (speedup 1.0000x reference)
#include <cuda_runtime.h>
#include <cuda_bf16.h>
#include <math.h>

#define BB   128
#define NN   1024
#define DIN  192
#define HH   128
#define KK   3
#define NTILES 16
#define TILE_N 64
#define UPD_THREADS 384

typedef unsigned int u32;

// -------- device scratch (no allocations allowed) --------
__device__ float g_inputs[(size_t)BB*NN*HH];   // 64 MB, LN'ed projected inputs
__device__ float g_slots[BB*KK*HH];
__device__ float g_qk[BB*KK*HH];               // q' = Wk^T (scale*q)
__device__ float g_qbk[BB*4];                  // (scale*q) . bk per slot
__device__ float g_updp[BB*NTILES*KK*HH];      // partial attn.inputs
__device__ float g_updsum[BB*NTILES*4];        // partial attn row sums

// transposed weights (coalesced thread-per-output access)
__device__ float g_WihT[128*384];
__device__ float g_WhhT[128*384];
__device__ float g_WvT[128*128];
__device__ float g_W1T[128*256];
__device__ float g_W2T[256*128];
__device__ float g_WqT[128*128];
// pre-split Wp (bf16 hi/lo), row-major [128][192]
__device__ __nv_bfloat16 g_Wph[128*192];
__device__ __nv_bfloat16 g_Wpl[128*192];

// bf16 split helpers
__device__ __forceinline__ void bsplit(float x, float& h, float& r) {
    __nv_bfloat16 b = __float2bfloat16_rn(x);
    h = __bfloat162float(b);
    r = x - h;
}
__device__ __forceinline__ u32 pk2(float lo, float hi) {
    __nv_bfloat162 t = __floats2bfloat162_rn(lo, hi);
    return *reinterpret_cast<u32*>(&t);
}

__device__ __forceinline__ void mma16816(float* c, u32 a0, u32 a1, u32 a2, u32 a3,
                                         u32 b0, u32 b1) {
    asm volatile(
        "mma.sync.aligned.m16n8k16.row.col.f32.bf16.bf16.f32 "
        "{%0,%1,%2,%3}, {%4,%5,%6,%7}, {%8,%9}, {%0,%1,%2,%3};"
        : "+f"(c[0]), "+f"(c[1]), "+f"(c[2]), "+f"(c[3])
        : "r"(a0), "r"(a1), "r"(a2), "r"(a3), "r"(b0), "r"(b1));
}

// ============================================================
// weight prep kernels (split so proj_ln is ncu's launch #6)
// ============================================================
__global__ void tr_gru(const float* __restrict__ Wih, const float* __restrict__ Whh)
{
    int idx = blockIdx.x * 256 + threadIdx.x;
    if (idx < 384*128) {
        int j = idx >> 7, i = idx & 127;
        g_WihT[i*384 + j] = Wih[idx];
        g_WhhT[i*384 + j] = Whh[idx];
    }
}
__global__ void tr_mlp(const float* __restrict__ W1, const float* __restrict__ W2)
{
    int idx = blockIdx.x * 256 + threadIdx.x;
    if (idx < 256*128) {
        int j = idx >> 7, i = idx & 127;
        g_W1T[i*256 + j] = W1[idx];
    }
    if (idx < 128*256) {
        int j = idx >> 8, i = idx & 255;
        g_W2T[i*128 + j] = W2[idx];
    }
}
__global__ void tr_small(const float* __restrict__ Wv, const float* __restrict__ Wq)
{
    int idx = blockIdx.x * 256 + threadIdx.x;
    if (idx < 128*128) {
        int j = idx >> 7, i = idx & 127;
        g_WvT[i*128 + j] = Wv[idx];
        g_WqT[i*128 + j] = Wq[idx];
    }
}
__global__ void tr_wp(const float* __restrict__ Wp)
{
    int idx = blockIdx.x * 256 + threadIdx.x;
    if (idx < 128*192) {
        float x = Wp[idx];
        __nv_bfloat16 h = __float2bfloat16_rn(x);
        g_Wph[idx] = h;
        g_Wpl[idx] = __float2bfloat16_rn(x - __bfloat162float(h));
    }
}

// ============================================================
// Kernel 1: inputs = LN(patch @ Wp^T + bp) via bf16x3 mma.sync.
// 128 rows/CTA, 1024 CTAs, 256 threads (8 warps, 16 rows each).
// ============================================================
#define RSTRIDE 400
#define AH_OFF  0
#define AL_OFF  (128*RSTRIDE)
#define WH_OFF  (2*128*RSTRIDE)
#define WL_OFF  (3*128*RSTRIDE)
#define PAR_OFF (4*128*RSTRIDE)
#define SM1_BYTES (PAR_OFF + 3*128*4)

__global__ __launch_bounds__(256) void proj_ln(
    const float* __restrict__ patch,
    const float* __restrict__ bp,
    const float* __restrict__ g_in, const float* __restrict__ b_in)
{
    extern __shared__ char smc[];
    float* bpS = reinterpret_cast<float*>(smc + PAR_OFF);
    float* gS  = bpS + 128;
    float* bS  = gS + 128;

    const int t    = threadIdx.x;
    const int warp = t >> 5;
    const int lane = t & 31;
    const int g    = lane >> 2;
    const int tig  = lane & 3;
    const long rowbase = (long)blockIdx.x * 128;

    if (t < 128) { bpS[t] = bp[t]; gS[t] = g_in[t]; bS[t] = b_in[t]; }

    // convert patch -> Ah/Al
    for (int idx = t; idx < 128*48; idx += 256) {
        int row = idx / 48;
        int c4  = idx % 48;
        float4 gv = *reinterpret_cast<const float4*>(patch + (rowbase + row)*DIN + c4*4);
        float h0,h1,h2,h3,r0,r1,r2,r3;
        bsplit(gv.x,h0,r0); bsplit(gv.y,h1,r1); bsplit(gv.z,h2,r2); bsplit(gv.w,h3,r3);
        int off = row*RSTRIDE + c4*8;
        *reinterpret_cast<uint2*>(smc + AH_OFF + off) = make_uint2(pk2(h0,h1), pk2(h2,h3));
        *reinterpret_cast<uint2*>(smc + AL_OFF + off) = make_uint2(pk2(r0,r1), pk2(r2,r3));
    }
    // copy pre-split Wp (bf16) -> Wh/Wl tiles (24 x 16B per 192-col row)
    for (int idx = t; idx < 128*24; idx += 256) {
        int row = idx / 24;
        int c16 = idx % 24;
        uint4 vh = *reinterpret_cast<const uint4*>(
            reinterpret_cast<const char*>(g_Wph) + row*384 + c16*16);
        uint4 vl = *reinterpret_cast<const uint4*>(
            reinterpret_cast<const char*>(g_Wpl) + row*384 + c16*16);
        *reinterpret_cast<uint4*>(smc + WH_OFF + row*RSTRIDE + c16*16) = vh;
        *reinterpret_cast<uint4*>(smc + WL_OFF + row*RSTRIDE + c16*16) = vl;
    }
    __syncthreads();

    float acc[16][4];
    #pragma unroll
    for (int nf = 0; nf < 16; nf++)
        #pragma unroll
        for (int i = 0; i < 4; i++) acc[nf][i] = 0.0f;

    const int r0 = 16*warp + g;
    const int aoff0 = r0 * RSTRIDE + tig * 4;

    #pragma unroll
    for (int pass = 0; pass < 3; pass++) {
        const char* A = smc + (pass == 1 ? AL_OFF : AH_OFF);
        const char* B = smc + (pass == 2 ? WL_OFF : WH_OFF);
        #pragma unroll
        for (int ks = 0; ks < 12; ks++) {
            int ao = aoff0 + ks*32;
            u32 a0 = *reinterpret_cast<const u32*>(A + ao);
            u32 a1 = *reinterpret_cast<const u32*>(A + ao + 8*RSTRIDE);
            u32 a2 = *reinterpret_cast<const u32*>(A + ao + 16);
            u32 a3 = *reinterpret_cast<const u32*>(A + ao + 8*RSTRIDE + 16);
            #pragma unroll
            for (int nf = 0; nf < 16; nf++) {
                int bo = (8*nf + g)*RSTRIDE + ks*32 + tig*4;
                u32 b0 = *reinterpret_cast<const u32*>(B + bo);
                u32 b1 = *reinterpret_cast<const u32*>(B + bo + 16);
                mma16816(acc[nf], a0, a1, a2, a3, b0, b1);
            }
        }
    }

    #pragma unroll
    for (int nf = 0; nf < 16; nf++) {
        int c = 8*nf + 2*tig;
        acc[nf][0] += bpS[c];   acc[nf][1] += bpS[c+1];
        acc[nf][2] += bpS[c];   acc[nf][3] += bpS[c+1];
    }
    float s0 = 0.f, q0 = 0.f, s1 = 0.f, q1 = 0.f;
    #pragma unroll
    for (int nf = 0; nf < 16; nf++) {
        s0 += acc[nf][0] + acc[nf][1];
        q0 += acc[nf][0]*acc[nf][0] + acc[nf][1]*acc[nf][1];
        s1 += acc[nf][2] + acc[nf][3];
        q1 += acc[nf][2]*acc[nf][2] + acc[nf][3]*acc[nf][3];
    }
    #pragma unroll
    for (int m = 1; m <= 2; m <<= 1) {
        s0 += __shfl_xor_sync(0xffffffffu, s0, m);
        q0 += __shfl_xor_sync(0xffffffffu, q0, m);
        s1 += __shfl_xor_sync(0xffffffffu, s1, m);
        q1 += __shfl_xor_sync(0xffffffffu, q1, m);
    }
    float mu0 = s0*(1.0f/128.0f), var0 = q0*(1.0f/128.0f) - mu0*mu0;
    float mu1 = s1*(1.0f/128.0f), var1 = q1*(1.0f/128.0f) - mu1*mu1;
    float rs0 = rsqrtf(var0 + 1e-5f);
    float rs1 = rsqrtf(var1 + 1e-5f);

    float* out0 = g_inputs + (rowbase + r0) * HH;
    float* out1 = g_inputs + (rowbase + r0 + 8) * HH;
    #pragma unroll
    for (int nf = 0; nf < 16; nf++) {
        int c = 8*nf + 2*tig;
        float2 y0 = make_float2((acc[nf][0]-mu0)*rs0*gS[c]   + bS[c],
                                (acc[nf][1]-mu0)*rs0*gS[c+1] + bS[c+1]);
        float2 y1 = make_float2((acc[nf][2]-mu1)*rs1*gS[c]   + bS[c],
                                (acc[nf][3]-mu1)*rs1*gS[c+1] + bS[c+1]);
        *reinterpret_cast<float2*>(out0 + c) = y0;
        *reinterpret_cast<float2*>(out1 + c) = y1;
    }
}

// ============================================================
// q computation from slots in smem `h` -> g_qk/g_qbk (UPD_THREADS threads).
// ============================================================
__device__ __forceinline__ void q_from_slots(
    const float* __restrict__ h,      // smem [384]
    float* __restrict__ s_ln, float* __restrict__ qs, float* __restrict__ pr,
    const float* __restrict__ bq,
    const float* __restrict__ Wk,  const float* __restrict__ bk,
    const float* __restrict__ g_s, const float* __restrict__ b_s,
    int b, int t)
{
    const int lane = t & 31;
    const int warp = t >> 5;

    if (warp < KK) {
        float x[4];
        float s = 0.0f, sq = 0.0f;
        #pragma unroll
        for (int m = 0; m < 4; m++) {
            x[m] = h[warp*128 + lane + 32*m];
            s += x[m]; sq += x[m]*x[m];
        }
        #pragma unroll
        for (int off = 16; off >= 1; off >>= 1) {
            s  += __shfl_xor_sync(0xffffffffu, s,  off);
            sq += __shfl_xor_sync(0xffffffffu, sq, off);
        }
        float mu   = s  * (1.0f/128.0f);
        float var  = sq * (1.0f/128.0f) - mu*mu;
        float rstd = rsqrtf(var + 1e-5f);
        #pragma unroll
        for (int m = 0; m < 4; m++) {
            int c = lane + 32*m;
            s_ln[warp*128 + c] = (x[m]-mu)*rstd*g_s[c] + b_s[c];
        }
    }
    __syncthreads();

    if (t < 128) {
        float a0 = 0.f, a1 = 0.f, a2 = 0.f;
        #pragma unroll 8
        for (int i = 0; i < 128; i++) {
            float wv = g_WqT[i*128 + t];
            a0 += s_ln[i]       * wv;
            a1 += s_ln[128 + i] * wv;
            a2 += s_ln[256 + i] * wv;
        }
        const float sc = 0.08838834764831843f;  // 1/sqrt(128)
        float bqv = bq[t];
        qs[t]       = (a0 + bqv) * sc;
        qs[128 + t] = (a1 + bqv) * sc;
        qs[256 + t] = (a2 + bqv) * sc;
    }
    __syncthreads();

    if (t < 128) {
        float a0 = 0.f, a1 = 0.f, a2 = 0.f;
        #pragma unroll 8
        for (int j = 0; j < 128; j++) {
            float wv = Wk[j*128 + t];
            a0 += qs[j]       * wv;
            a1 += qs[128 + j] * wv;
            a2 += qs[256 + j] * wv;
        }
        g_qk[b*384 + t]       = a0;
        g_qk[b*384 + 128 + t] = a1;
        g_qk[b*384 + 256 + t] = a2;

        float bkt = bk[t];
        pr[t]       = qs[t]       * bkt;
        pr[128 + t] = qs[128 + t] * bkt;
        pr[256 + t] = qs[256 + t] * bkt;
    }
    __syncthreads();
    if (t < KK) {
        float s = 0.0f;
        #pragma unroll 8
        for (int i = 0; i < 128; i++) s += pr[t*128 + i];
        g_qbk[b*4 + t] = s;
    }
}

// ============================================================
// init_q: slots init + first q. grid=BB, UPD_THREADS threads.
// ============================================================
__global__ __launch_bounds__(UPD_THREADS) void init_q(
    const float* __restrict__ noise,
    const float* __restrict__ mu,  const float* __restrict__ ls,
    const float* __restrict__ bq,
    const float* __restrict__ Wk,  const float* __restrict__ bk,
    const float* __restrict__ g_s, const float* __restrict__ b_s)
{
    __shared__ float h[384], s_ln[384], qs[384], pr[384];
    const int t = threadIdx.x;
    const int b = blockIdx.x;

    if (t < 384) {
        float v = mu[t] + expf(ls[t]) * noise[b*384 + t];
        g_slots[b*384 + t] = v;
        h[t] = v;
    }
    __syncthreads();
    q_from_slots(h, s_ln, qs, pr, bq, Wk, bk, g_s, b_s, b, t);
}

// ============================================================
// attn_tile v3: TILE_N=64, ~38KB smem -> 6 CTAs/SM.
// grid = BB*NTILES (2048), 256 threads. 4 threads per token for logits.
// ============================================================
#define TSTRIDE 132
#define ATTN_SM ((TILE_N*TSTRIDE + 384 + 192 + 384 + 8) * 4)

__global__ __launch_bounds__(256) void attn_tile(float* __restrict__ out_attn,
                                                 int write_attn)
{
    extern __shared__ float dyn[];
    float* tile   = dyn;                    // [64][132]
    float* qsm    = dyn + TILE_N*TSTRIDE;   // [3][128]
    float* attn_s = qsm + 384;              // [3][64]
    float* red    = attn_s + 192;           // [384]
    float* red2   = red + 384;              // [8]

    const int t = threadIdx.x;
    const int b      = blockIdx.x >> 4;
    const int tile_i = blockIdx.x & 15;
    const int n0     = tile_i * TILE_N;

    const float* ib = g_inputs + ((size_t)b * NN + n0) * HH;

    // stage input tile (64 rows x 32 float4)
    for (int idx = t; idx < TILE_N*32; idx += 256) {
        int row = idx >> 5;
        int c4  = idx & 31;
        float4 v = *reinterpret_cast<const float4*>(ib + row*HH + c4*4);
        *reinterpret_cast<float4*>(tile + row*TSTRIDE + c4*4) = v;
    }
    // stage q
    for (int idx = t; idx < 384; idx += 256) qsm[idx] = g_qk[b*384 + idx];
    float qb0 = g_qbk[b*4 + 0];
    float qb1 = g_qbk[b*4 + 1];
    float qb2 = g_qbk[b*4 + 2];
    __syncthreads();

    // logits: 4 threads per token, 32 dims each, 2 shuffles
    {
        const int n = t >> 2;
        const int p = t & 3;
        const float* tr = tile + n*TSTRIDE + p*32;
        const float* q0 = qsm + p*32;
        const float* q1 = qsm + 128 + p*32;
        const float* q2 = qsm + 256 + p*32;
        float p0 = 0.f, p1 = 0.f, p2 = 0.f;
        #pragma unroll
        for (int j = 0; j < 8; j++) {
            float4 x = *reinterpret_cast<const float4*>(tr + j*4);
            float4 a = *reinterpret_cast<const float4*>(q0 + j*4);
            float4 bqv = *reinterpret_cast<const float4*>(q1 + j*4);
            float4 c = *reinterpret_cast<const float4*>(q2 + j*4);
            p0 += x.x*a.x   + x.y*a.y   + x.z*a.z   + x.w*a.w;
            p1 += x.x*bqv.x + x.y*bqv.y + x.z*bqv.z + x.w*bqv.w;
            p2 += x.x*c.x   + x.y*c.y   + x.z*c.z   + x.w*c.w;
        }
        #pragma unroll
        for (int off = 1; off <= 2; off <<= 1) {
            p0 += __shfl_xor_sync(0xffffffffu, p0, off);
            p1 += __shfl_xor_sync(0xffffffffu, p1, off);
            p2 += __shfl_xor_sync(0xffffffffu, p2, off);
        }
        if (p == 0) {
            p0 += qb0; p1 += qb1; p2 += qb2;
            float mx = fmaxf(p0, fmaxf(p1, p2));
            float e0 = expf(p0 - mx), e1 = expf(p1 - mx), e2 = expf(p2 - mx);
            float inv = 1.0f / (e0 + e1 + e2);
            attn_s[n]       = e0*inv;
            attn_s[64 + n]  = e1*inv;
            attn_s[128 + n] = e2*inv;
        }
    }
    __syncthreads();

    if (write_attn) {
        if (t < 192) {
            int kk = t / 64;
            int n  = t % 64;
            out_attn[b*KK*NN + kk*NN + n0 + n] = attn_s[t];
        }
    }

    // partial attn.inputs + rowsums; thread owns (d, half), sums 32 rows
    const int d    = t & 127;
    const int half = t >> 7;
    const float* tcol = tile + (half*32)*TSTRIDE + d;
    float u0 = 0.f, u1 = 0.f, u2 = 0.f;
    float as0 = 0.f, as1 = 0.f, as2 = 0.f;
    #pragma unroll 4
    for (int n = 0; n < 32; n++) {
        float vv = tcol[n*TSTRIDE];
        int na = half*32 + n;
        float a0 = attn_s[na];
        float a1 = attn_s[64 + na];
        float a2 = attn_s[128 + na];
        u0 += a0 * vv;  u1 += a1 * vv;  u2 += a2 * vv;
        as0 += a0; as1 += a1; as2 += a2;
    }
    if (half == 1) {
        red[d] = u0; red[128+d] = u1; red[256+d] = u2;
        if (d == 0) { red2[0] = as0; red2[1] = as1; red2[2] = as2; }
    }
    __syncthreads();
    if (half == 0) {
        float* dst = g_updp + ((size_t)(b*NTILES + tile_i))*384;
        dst[d]       = u0 + red[d];
        dst[128 + d] = u1 + red[128+d];
        dst[256 + d] = u2 + red[256+d];
        if (d == 0) {
            float* ds = g_updsum + (size_t)(b*NTILES + tile_i)*4;
            ds[0] = as0 + red2[0];
            ds[1] = as1 + red2[1];
            ds[2] = as2 + red2[2];
        }
    }
}

// ============================================================
// upd_q: reduce partials, Wv/bv, GRU, LN, MLP; then next-iter q.
// grid=BB, UPD_THREADS threads, transposed (coalesced) weights.
// ============================================================
__global__ __launch_bounds__(UPD_THREADS) void upd_q(
    const float* __restrict__ bv,
    const float* __restrict__ bih, const float* __restrict__ bhh,
    const float* __restrict__ g_m, const float* __restrict__ b_m,
    const float* __restrict__ b1,  const float* __restrict__ b2,
    const float* __restrict__ bq,
    const float* __restrict__ Wk,  const float* __restrict__ bk,
    const float* __restrict__ g_s, const float* __restrict__ b_s,
    float* __restrict__ out_slots, int last)
{
    __shared__ float h_prev[384];
    __shared__ float ared[384];
    __shared__ float asum[4];
    __shared__ float updf[384];
    __shared__ float gi_s[1152];
    __shared__ float gh_s[1152];
    __shared__ float snew[384];
    __shared__ float hm[384];
    __shared__ float a1_s[768];
    __shared__ float fin[384];

    const int t = threadIdx.x;
    const int lane = t & 31;
    const int warp = t >> 5;
    const int b = blockIdx.x;

    if (t < 384) h_prev[t] = g_slots[b*384 + t];
    if (t < 128) {
        #pragma unroll
        for (int kk = 0; kk < 3; kk++) {
            float s = 0.0f;
            const float* src = g_updp + (size_t)b*NTILES*384 + kk*128 + t;
            #pragma unroll
            for (int tl = 0; tl < NTILES; tl++) s += src[tl*384];
            ared[kk*128 + t] = s;
        }
    } else if (t < 131) {
        int s = t - 128;
        float acc = 0.0f;
        #pragma unroll
        for (int tl = 0; tl < NTILES; tl++) acc += g_updsum[(size_t)(b*NTILES + tl)*4 + s];
        asum[s] = acc;
    }
    __syncthreads();

    // updates = ared @ Wv^T + asum*bv   (coalesced WvT)
    if (t < 128) {
        float u0 = 0.f, u1 = 0.f, u2 = 0.f;
        #pragma unroll 8
        for (int i = 0; i < 128; i++) {
            float wv = g_WvT[i*128 + t];
            u0 += ared[i]       * wv;
            u1 += ared[128 + i] * wv;
            u2 += ared[256 + i] * wv;
        }
        float bvt = bv[t];
        updf[t]       = u0 + asum[0]*bvt;
        updf[128 + t] = u1 + asum[1]*bvt;
        updf[256 + t] = u2 + asum[2]*bvt;
    }
    __syncthreads();

    // GRU gate GEMMs (coalesced WihT/WhhT, one output per thread)
    {
        float ai0=0.f, ai1=0.f, ai2=0.f, ah0=0.f, ah1=0.f, ah2=0.f;
        #pragma unroll 8
        for (int i = 0; i < 128; i++) {
            float wiv = g_WihT[i*384 + t];
            float whv = g_WhhT[i*384 + t];
            ai0 += updf[i]        * wiv;
            ai1 += updf[128 + i]  * wiv;
            ai2 += updf[256 + i]  * wiv;
            ah0 += h_prev[i]       * whv;
            ah1 += h_prev[128 + i] * whv;
            ah2 += h_prev[256 + i] * whv;
        }
        float bi = bih[t], bh = bhh[t];
        gi_s[t]        = ai0 + bi;
        gi_s[384 + t]  = ai1 + bi;
        gi_s[768 + t]  = ai2 + bi;
        gh_s[t]        = ah0 + bh;
        gh_s[384 + t]  = ah1 + bh;
        gh_s[768 + t]  = ah2 + bh;
    }
    __syncthreads();

    if (t < 128) {
        #pragma unroll
        for (int kk = 0; kk < 3; kk++) {
            float ir  = gi_s[kk*384 + t];
            float iz  = gi_s[kk*384 + 128 + t];
            float inn = gi_s[kk*384 + 256 + t];
            float hr  = gh_s[kk*384 + t];
            float hz  = gh_s[kk*384 + 128 + t];
            float hn  = gh_s[kk*384 + 256 + t];
            float r = 1.0f / (1.0f + expf(-(ir + hr)));
            float z = 1.0f / (1.0f + expf(-(iz + hz)));
            float nn = tanhf(inn + r*hn);
            snew[kk*128 + t] = (1.0f - z)*nn + z*h_prev[kk*128 + t];
        }
    }
    __syncthreads();

    // hm = LN(snew)*g_m + b_m
    if (warp < KK) {
        float x[4];
        float s = 0.0f, sq = 0.0f;
        #pragma unroll
        for (int m = 0; m < 4; m++) {
            x[m] = snew[warp*128 + lane + 32*m];
            s += x[m]; sq += x[m]*x[m];
        }
        #pragma unroll
        for (int off = 16; off >= 1; off >>= 1) {
            s  += __shfl_xor_sync(0xffffffffu, s,  off);
            sq += __shfl_xor_sync(0xffffffffu, sq, off);
        }
        float mu   = s  * (1.0f/128.0f);
        float var  = sq * (1.0f/128.0f) - mu*mu;
        float rstd = rsqrtf(var + 1e-5f);
        #pragma unroll
        for (int m = 0; m < 4; m++) {
            int c = lane + 32*m;
            hm[warp*128 + c] = (x[m]-mu)*rstd*g_m[c] + b_m[c];
        }
    }
    __syncthreads();

    // a1 = gelu_exact(hm @ W1^T + b1)   (coalesced W1T, 256 outputs)
    if (t < 256) {
        float a0 = 0.f, a1v = 0.f, a2 = 0.f;
        #pragma unroll 8
        for (int i = 0; i < 128; i++) {
            float wv = g_W1T[i*256 + t];
            a0  += hm[i]       * wv;
            a1v += hm[128 + i] * wv;
            a2  += hm[256 + i] * wv;
        }
        float bb = b1[t];
        float x0 = a0 + bb, x1 = a1v + bb, x2 = a2 + bb;
        const float is2 = 0.70710678118654752f;
        a1_s[t]        = 0.5f * x0 * (1.0f + erff(x0 * is2));
        a1_s[256 + t]  = 0.5f * x1 * (1.0f + erff(x1 * is2));
        a1_s[512 + t]  = 0.5f * x2 * (1.0f + erff(x2 * is2));
    }
    __syncthreads();

    // final slots = snew + a1 @ W2^T + b2   (coalesced W2T)
    if (t < 128) {
        float a0 = 0.f, a1v = 0.f, a2 = 0.f;
        #pragma unroll 8
        for (int i = 0; i < 256; i++) {
            float wv = g_W2T[i*128 + t];
            a0  += a1_s[i]       * wv;
            a1v += a1_s[256 + i] * wv;
            a2  += a1_s[512 + i] * wv;
        }
        float bb = b2[t];
        int base = b*384;
        float f0 = snew[t]       + a0  + bb;
        float f1 = snew[128 + t] + a1v + bb;
        float f2 = snew[256 + t] + a2  + bb;
        fin[t] = f0; fin[128 + t] = f1; fin[256 + t] = f2;
        g_slots[base + t]       = f0;
        g_slots[base + 128 + t] = f1;
        g_slots[base + 256 + t] = f2;
        if (last) {
            out_slots[base + t]       = f0;
            out_slots[base + 128 + t] = f1;
            out_slots[base + 256 + t] = f2;
        }
    }
    __syncthreads();

    if (!last) {
        q_from_slots(fin, gi_s, gi_s + 384, gi_s + 768,
                     bq, Wk, bk, g_s, b_s, b, t);
    }
}

// ============================================================
extern "C" void kernel_launch(void* const* d_in, const int* in_sizes, int n_in,
                              void* d_out, int out_size)
{
    const float* patch   = (const float*)d_in[0];
    const float* noise   = (const float*)d_in[1];
    const float* slot_mu = (const float*)d_in[2];
    const float* slot_ls = (const float*)d_in[3];
    const float* Wp  = (const float*)d_in[4];
    const float* bp  = (const float*)d_in[5];
    const float* g_in= (const float*)d_in[6];
    const float* b_in= (const float*)d_in[7];
    const float* Wq  = (const float*)d_in[8];
    const float* bq  = (const float*)d_in[9];
    const float* Wk  = (const float*)d_in[10];
    const float* bk  = (const float*)d_in[11];
    const float* Wv  = (const float*)d_in[12];
    const float* bv  = (const float*)d_in[13];
    const float* Wih = (const float*)d_in[14];
    const float* bih = (const float*)d_in[15];
    const float* Whh = (const float*)d_in[16];
    const float* bhh = (const float*)d_in[17];
    const float* g_s = (const float*)d_in[18];
    const float* b_s = (const float*)d_in[19];
    const float* W1  = (const float*)d_in[20];
    const float* b1  = (const float*)d_in[21];
    const float* W2  = (const float*)d_in[22];
    const float* b2  = (const float*)d_in[23];
    const float* g_m = (const float*)d_in[24];
    const float* b_m = (const float*)d_in[25];

    float* out       = (float*)d_out;
    float* out_slots = out;                     // B*K*H = 49152
    float* out_attn  = out + BB*KK*HH;          // B*K*N = 393216

    cudaFuncSetAttribute(proj_ln, cudaFuncAttributeMaxDynamicSharedMemorySize, SM1_BYTES);
    cudaFuncSetAttribute(attn_tile, cudaFuncAttributeMaxDynamicSharedMemorySize, ATTN_SM);

    // launches 1-5 (proj_ln is #6 -> captured by ncu -s 5 -c 1)
    tr_gru<<<192, 256>>>(Wih, Whh);
    tr_mlp<<<128, 256>>>(W1, W2);
    tr_small<<<64, 256>>>(Wv, Wq);
    tr_wp<<<96, 256>>>(Wp);
    init_q<<<BB, UPD_THREADS>>>(noise, slot_mu, slot_ls, bq, Wk, bk, g_s, b_s);
    proj_ln<<<(BB*NN)/128, 256, SM1_BYTES>>>(patch, bp, g_in, b_in);
    for (int it = 0; it < 3; it++) {
        attn_tile<<<BB*NTILES, 256, ATTN_SM>>>(out_attn, it == 2 ? 1 : 0);
        upd_q<<<BB, UPD_THREADS>>>(bv, bih, bhh, g_m, b_m, b1, b2,
                                   bq, Wk, bk, g_s, b_s,
                                   out_slots, it == 2 ? 1 : 0);
    }
}